// round 1
// baseline (speedup 1.0000x reference)
#include <cuda_runtime.h>
#include <math.h>

#define EPS 1e-5f
#define MAX_NORM 0.95f
#define D 128
#define MAXN 50000

// ---------------- scratch (static device globals; no runtime allocation) ----
__device__ float g_v[MAXN * D];    // tangent vectors (GEMM input)
__device__ float g_t[MAXN * D];    // message tangents (scatter source)
__device__ float g_sum[MAXN * D];  // segment sums
__device__ float g_h[MAXN * D];    // node state between layers
__device__ float g_cnt[MAXN];      // in-degree counts

// ---------------- scalar chains (all maps scale the vector by f(norm)) ------
__device__ __forceinline__ float s_log0(float n) {
    float nm  = fmaxf(n, EPS);
    float arg = fminf(nm, 1.0f - EPS);
    return atanhf(arg) / nm;
}
// exp0 -> proj -> log0 composite multiplier (used for msg output and agg prep)
__device__ __forceinline__ float chain_epl(float n) {
    float nm = fmaxf(n, EPS);
    float a  = tanhf(nm) / nm;          // exp0 scale
    float na = n * a;                   // norm after exp0
    float b  = (na > MAX_NORM) ? MAX_NORM / fmaxf(na, EPS) : 1.0f;  // proj
    float nb = na * b;
    float nbm = fmaxf(nb, EPS);
    float arg = fminf(nbm, 1.0f - EPS);
    float c  = atanhf(arg) / nbm;       // log0 scale
    return a * b * c;
}
// exp0 -> proj only (final output of hyp_linear)
__device__ __forceinline__ float chain_ep(float n) {
    float nm = fmaxf(n, EPS);
    float a  = tanhf(nm) / nm;
    float na = n * a;
    float b  = (na > MAX_NORM) ? MAX_NORM / fmaxf(na, EPS) : 1.0f;
    return a * b;
}

// ---------------- zero fill -------------------------------------------------
__global__ void zero_kernel(float* __restrict__ p, int n4) {
    int i = blockIdx.x * blockDim.x + threadIdx.x;
    if (i < n4) reinterpret_cast<float4*>(p)[i] = make_float4(0.f, 0.f, 0.f, 0.f);
}

// ---------------- degree count ----------------------------------------------
__global__ void count_kernel(const int* __restrict__ dst, int E) {
    int e = blockIdx.x * blockDim.x + threadIdx.x;
    if (e < E) atomicAdd(&g_cnt[dst[e]], 1.0f);
}

// ---------------- prep: v = log0(h) (warp per row) --------------------------
__global__ void prep_log0_kernel(const float* __restrict__ in, float* __restrict__ out, int N) {
    int w    = (blockIdx.x * blockDim.x + threadIdx.x) >> 5;
    int lane = threadIdx.x & 31;
    if (w >= N) return;
    float4 v = *reinterpret_cast<const float4*>(&in[(size_t)w * D + lane * 4]);
    float p = v.x * v.x + v.y * v.y + v.z * v.z + v.w * v.w;
#pragma unroll
    for (int off = 16; off; off >>= 1) p += __shfl_xor_sync(0xffffffffu, p, off);
    float s = s_log0(sqrtf(p));
    v.x *= s; v.y *= s; v.z *= s; v.w *= s;
    *reinterpret_cast<float4*>(&out[(size_t)w * D + lane * 4]) = v;
}

// ---------------- prep: v = log0(proj(exp0(sum/cnt))) -----------------------
__global__ void prep_agg_kernel(const float* __restrict__ sum, float* __restrict__ out, int N) {
    int w    = (blockIdx.x * blockDim.x + threadIdx.x) >> 5;
    int lane = threadIdx.x & 31;
    if (w >= N) return;
    float inv = 1.0f / fmaxf(g_cnt[w], 1.0f);
    float4 v = *reinterpret_cast<const float4*>(&sum[(size_t)w * D + lane * 4]);
    v.x *= inv; v.y *= inv; v.z *= inv; v.w *= inv;
    float p = v.x * v.x + v.y * v.y + v.z * v.z + v.w * v.w;
#pragma unroll
    for (int off = 16; off; off >>= 1) p += __shfl_xor_sync(0xffffffffu, p, off);
    float s = chain_epl(sqrtf(p));
    v.x *= s; v.y *= s; v.z *= s; v.w *= s;
    *reinterpret_cast<float4*>(&out[(size_t)w * D + lane * 4]) = v;
}

// ---------------- scatter: sum[dst] += t[src] (warp per edge) ---------------
__global__ void scatter_kernel(const int* __restrict__ src, const int* __restrict__ dst, int E) {
    int e    = (blockIdx.x * blockDim.x + threadIdx.x) >> 5;
    int lane = threadIdx.x & 31;
    if (e >= E) return;
    int s = __ldg(&src[e]);
    int d = __ldg(&dst[e]);
    float4 tv = *reinterpret_cast<const float4*>(&g_t[(size_t)s * D + lane * 4]);
    float* base = &g_sum[(size_t)d * D + lane * 4];
    atomicAdd(base + 0, tv.x);
    atomicAdd(base + 1, tv.y);
    atomicAdd(base + 2, tv.z);
    atomicAdd(base + 3, tv.w);
}

// ---------------- GEMM + fused hyperbolic epilogue --------------------------
// out[m][j] = scale(||u_m||) * u_m[j],  u = V @ W^T + b
// mode 0 (msg): scale = exp0->proj->log0 composite (output is tangent t)
// mode 1 (upd): scale = exp0->proj            (output is ball point h)
#define KC 64
#define AS 132  // padded smem stride

__global__ __launch_bounds__(256) void gemm_hyp_kernel(
    const float* __restrict__ V, const float* __restrict__ W,
    const float* __restrict__ bias, float* __restrict__ out,
    int N, int mode)
{
    extern __shared__ float smem[];
    float* Ast    = smem;                 // [KC][AS]  (k-major, transposed A)
    float* Wts    = Ast + KC * AS;        // [KC][AS]  (k-major, transposed W)
    float* bias_s = Wts + KC * AS;        // [128]
    float* red    = bias_s + D;           // [128][17]
    float* scl    = red + D * 17;         // [128]

    int tid = threadIdx.x;
    int tx = tid & 15, ty = tid >> 4;
    int m0 = blockIdx.x * 128;

    if (tid < D) bias_s[tid] = bias[tid];

    float acc[8][8];
#pragma unroll
    for (int i = 0; i < 8; i++)
#pragma unroll
        for (int j = 0; j < 8; j++) acc[i][j] = 0.0f;

    for (int kc = 0; kc < D; kc += KC) {
        __syncthreads();
        // load A tile transposed: Ast[k][m], 128 rows x KC cols
#pragma unroll
        for (int i = 0; i < 8; i++) {
            int idx = tid + i * 256;        // 0..2047 float4 slots
            int row = idx >> 4;
            int k4  = idx & 15;
            float4 val = make_float4(0.f, 0.f, 0.f, 0.f);
            int gm = m0 + row;
            if (gm < N) val = *reinterpret_cast<const float4*>(&V[(size_t)gm * D + kc + k4 * 4]);
            int kk = k4 * 4;
            Ast[(kk + 0) * AS + row] = val.x;
            Ast[(kk + 1) * AS + row] = val.y;
            Ast[(kk + 2) * AS + row] = val.z;
            Ast[(kk + 3) * AS + row] = val.w;
        }
        // load W tile transposed: Wts[k][j]
#pragma unroll
        for (int i = 0; i < 8; i++) {
            int idx = tid + i * 256;
            int j  = idx >> 4;
            int k4 = idx & 15;
            float4 val = *reinterpret_cast<const float4*>(&W[(size_t)j * D + kc + k4 * 4]);
            int kk = k4 * 4;
            Wts[(kk + 0) * AS + j] = val.x;
            Wts[(kk + 1) * AS + j] = val.y;
            Wts[(kk + 2) * AS + j] = val.z;
            Wts[(kk + 3) * AS + j] = val.w;
        }
        __syncthreads();
#pragma unroll 8
        for (int k = 0; k < KC; k++) {
            float4 a0 = *reinterpret_cast<float4*>(&Ast[k * AS + tx * 4]);
            float4 a1 = *reinterpret_cast<float4*>(&Ast[k * AS + 64 + tx * 4]);
            float4 b0 = *reinterpret_cast<float4*>(&Wts[k * AS + ty * 4]);
            float4 b1 = *reinterpret_cast<float4*>(&Wts[k * AS + 64 + ty * 4]);
            float af[8] = {a0.x, a0.y, a0.z, a0.w, a1.x, a1.y, a1.z, a1.w};
            float bf[8] = {b0.x, b0.y, b0.z, b0.w, b1.x, b1.y, b1.z, b1.w};
#pragma unroll
            for (int i = 0; i < 8; i++)
#pragma unroll
                for (int j = 0; j < 8; j++) acc[i][j] += af[i] * bf[j];
        }
    }

    // epilogue: bias add + per-row sumsq partials
    int rows[8], cols[8];
#pragma unroll
    for (int i = 0; i < 4; i++) { rows[i] = tx * 4 + i; rows[i + 4] = 64 + tx * 4 + i; }
#pragma unroll
    for (int j = 0; j < 4; j++) { cols[j] = ty * 4 + j; cols[j + 4] = 64 + ty * 4 + j; }

#pragma unroll
    for (int i = 0; i < 8; i++) {
        float p = 0.0f;
#pragma unroll
        for (int j = 0; j < 8; j++) {
            float u = acc[i][j] + bias_s[cols[j]];
            acc[i][j] = u;
            p += u * u;
        }
        red[rows[i] * 17 + ty] = p;
    }
    __syncthreads();
    if (tid < D) {
        float s = 0.0f;
#pragma unroll
        for (int t = 0; t < 16; t++) s += red[tid * 17 + t];
        float n = sqrtf(s);
        scl[tid] = (mode == 0) ? chain_epl(n) : chain_ep(n);
    }
    __syncthreads();
#pragma unroll
    for (int i = 0; i < 8; i++) {
        int gm = m0 + rows[i];
        if (gm >= N) continue;
        float s = scl[rows[i]];
        float4 o0 = make_float4(acc[i][0] * s, acc[i][1] * s, acc[i][2] * s, acc[i][3] * s);
        float4 o1 = make_float4(acc[i][4] * s, acc[i][5] * s, acc[i][6] * s, acc[i][7] * s);
        *reinterpret_cast<float4*>(&out[(size_t)gm * D + ty * 4])      = o0;
        *reinterpret_cast<float4*>(&out[(size_t)gm * D + 64 + ty * 4]) = o1;
    }
}

// ---------------- host ------------------------------------------------------
extern "C" void kernel_launch(void* const* d_in, const int* in_sizes, int n_in,
                              void* d_out, int out_size)
{
    const float* x     = (const float*)d_in[0];
    const int*   ei    = (const int*)d_in[1];
    const float* msg_W = (const float*)d_in[2];
    const float* msg_b = (const float*)d_in[3];
    const float* upd_W = (const float*)d_in[4];
    const float* upd_b = (const float*)d_in[5];
    float* outp = (float*)d_out;

    int N = in_sizes[0] / D;
    int E = in_sizes[1] / 2;
    int L = in_sizes[3] / D;
    if (N > MAXN) return;

    const int* src = ei;
    const int* dst = ei + E;

    float *p_v, *p_t, *p_sum, *p_h, *p_cnt;
    cudaGetSymbolAddress((void**)&p_v,   g_v);
    cudaGetSymbolAddress((void**)&p_t,   g_t);
    cudaGetSymbolAddress((void**)&p_sum, g_sum);
    cudaGetSymbolAddress((void**)&p_h,   g_h);
    cudaGetSymbolAddress((void**)&p_cnt, g_cnt);

    static bool attr_done = false;
    const int SMEM = (KC * AS * 2 + D + D * 17 + D) * sizeof(float);
    if (!attr_done) {
        cudaFuncSetAttribute(gemm_hyp_kernel, cudaFuncAttributeMaxDynamicSharedMemorySize, SMEM);
        attr_done = true;
    }

    int nd4 = N * D / 4;
    // degree counts (edge-structure only: once per call, shared by all layers)
    zero_kernel<<<(N / 4 + 255) / 256, 256>>>(p_cnt, N / 4);
    count_kernel<<<(E + 255) / 256, 256>>>(dst, E);

    int gemm_blocks  = (N + 127) / 128;
    int warp_blocksN = (N * 32 + 255) / 256;
    int warp_blocksE = (E * 32 + 255) / 256;

    const float* h_in = x;
    for (int l = 0; l < L; l++) {
        // message hyp_linear fused with the following log0 (tangent output)
        prep_log0_kernel<<<warp_blocksN, 256>>>(h_in, p_v, N);
        gemm_hyp_kernel<<<gemm_blocks, 256, SMEM>>>(p_v, msg_W + (size_t)l * D * D,
                                                    msg_b + (size_t)l * D, p_t, N, /*mode=*/0);
        // tangent-space mean aggregation
        zero_kernel<<<(nd4 + 255) / 256, 256>>>(p_sum, nd4);
        scatter_kernel<<<warp_blocksE, 256>>>(src, dst, E);
        prep_agg_kernel<<<warp_blocksN, 256>>>(p_sum, p_v, N);
        // update hyp_linear (ball-point output)
        float* h_out = (l == L - 1) ? outp : p_h;
        gemm_hyp_kernel<<<gemm_blocks, 256, SMEM>>>(p_v, upd_W + (size_t)l * D * D,
                                                    upd_b + (size_t)l * D, h_out, N, /*mode=*/1);
        h_in = p_h;
    }
}

// round 2
// speedup vs baseline: 2.0824x; 2.0824x over previous
#include <cuda_runtime.h>
#include <math.h>

#define EPS 1e-5f
#define MAX_NORM 0.95f
#define D 128
#define MAXN 50000
#define MAXE 800000

// ---------------- scratch (static device globals) ---------------------------
__device__ float g_v[MAXN * D];    // tangent vectors (GEMM input)
__device__ float g_t[MAXN * D];    // message tangents (gather source)
__device__ float g_h[MAXN * D];    // inter-layer tangent state
__device__ int   g_deg[MAXN];      // in-degree
__device__ int   g_off[MAXN + 1];  // CSR offsets
__device__ int   g_cur[MAXN];      // CSR fill cursors
__device__ int   g_csrc[MAXE];     // CSR src ids grouped by dst

// ---------------- scalar chains ---------------------------------------------
__device__ __forceinline__ float s_log0(float n) {
    float nm  = fmaxf(n, EPS);
    float arg = fminf(nm, 1.0f - EPS);
    return atanhf(arg) / nm;
}
__device__ __forceinline__ float chain_epl(float n) {
    float nm = fmaxf(n, EPS);
    float a  = tanhf(nm) / nm;
    float na = n * a;
    float b  = (na > MAX_NORM) ? MAX_NORM / fmaxf(na, EPS) : 1.0f;
    float nb = na * b;
    float nbm = fmaxf(nb, EPS);
    float arg = fminf(nbm, 1.0f - EPS);
    float c  = atanhf(arg) / nbm;
    return a * b * c;
}
__device__ __forceinline__ float chain_ep(float n) {
    float nm = fmaxf(n, EPS);
    float a  = tanhf(nm) / nm;
    float na = n * a;
    float b  = (na > MAX_NORM) ? MAX_NORM / fmaxf(na, EPS) : 1.0f;
    return a * b;
}

// ---------------- CSR construction ------------------------------------------
__global__ void zero_int_kernel(int* __restrict__ p, int n) {
    int i = blockIdx.x * blockDim.x + threadIdx.x;
    if (i < n) p[i] = 0;
}
__global__ void hist_kernel(const int* __restrict__ dst, int E) {
    int e = blockIdx.x * blockDim.x + threadIdx.x;
    if (e < E) atomicAdd(&g_deg[dst[e]], 1);
}
// single-block exclusive scan of g_deg -> g_off, g_cur
__global__ void scan_kernel(int N) {
    int lane = threadIdx.x & 31, wid = threadIdx.x >> 5;
    __shared__ int wsum[32];
    __shared__ int running;
    if (threadIdx.x == 0) running = 0;
    __syncthreads();
    for (int base = 0; base < N; base += 1024) {
        int i = base + (int)threadIdx.x;
        int v = (i < N) ? g_deg[i] : 0;
        int x = v;
#pragma unroll
        for (int o = 1; o < 32; o <<= 1) {
            int y = __shfl_up_sync(0xffffffffu, x, o);
            if (lane >= o) x += y;
        }
        if (lane == 31) wsum[wid] = x;
        __syncthreads();
        if (wid == 0) {
            int s = wsum[lane];
#pragma unroll
            for (int o = 1; o < 32; o <<= 1) {
                int y = __shfl_up_sync(0xffffffffu, s, o);
                if (lane >= o) s += y;
            }
            wsum[lane] = s;
        }
        __syncthreads();
        int warp_prefix = (wid == 0) ? 0 : wsum[wid - 1];
        int excl = running + warp_prefix + (x - v);
        if (i < N) { g_off[i] = excl; g_cur[i] = excl; }
        int tile_total = wsum[31];
        __syncthreads();
        if (threadIdx.x == 0) running += tile_total;
        __syncthreads();
    }
    if (threadIdx.x == 0) g_off[N] = running;
}
__global__ void fill_kernel(const int* __restrict__ src, const int* __restrict__ dst, int E) {
    int e = blockIdx.x * blockDim.x + threadIdx.x;
    if (e < E) {
        int p = atomicAdd(&g_cur[dst[e]], 1);
        g_csrc[p] = src[e];
    }
}

// ---------------- prep: v = log0(x) (warp per row, layer 0 only) ------------
__global__ void prep_log0_kernel(const float* __restrict__ in, float* __restrict__ out, int N) {
    int w    = (blockIdx.x * blockDim.x + threadIdx.x) >> 5;
    int lane = threadIdx.x & 31;
    if (w >= N) return;
    float4 v = *reinterpret_cast<const float4*>(&in[(size_t)w * D + lane * 4]);
    float p = v.x * v.x + v.y * v.y + v.z * v.z + v.w * v.w;
#pragma unroll
    for (int off = 16; off; off >>= 1) p += __shfl_xor_sync(0xffffffffu, p, off);
    float s = s_log0(sqrtf(p));
    v.x *= s; v.y *= s; v.z *= s; v.w *= s;
    *reinterpret_cast<float4*>(&out[(size_t)w * D + lane * 4]) = v;
}

// ---------------- fused gather + mean + chain_epl (warp per node) -----------
__global__ void agg_kernel(float* __restrict__ out, int N) {
    int w    = (blockIdx.x * blockDim.x + threadIdx.x) >> 5;
    int lane = threadIdx.x & 31;
    if (w >= N) return;
    int beg = g_off[w], end = g_off[w + 1];
    float ax = 0.f, ay = 0.f, az = 0.f, aw = 0.f;
    int e = beg;
    int col = lane * 4;
    for (; e + 4 <= end; e += 4) {
        int s0 = g_csrc[e], s1 = g_csrc[e + 1], s2 = g_csrc[e + 2], s3 = g_csrc[e + 3];
        float4 v0 = *reinterpret_cast<const float4*>(&g_t[(size_t)s0 * D + col]);
        float4 v1 = *reinterpret_cast<const float4*>(&g_t[(size_t)s1 * D + col]);
        float4 v2 = *reinterpret_cast<const float4*>(&g_t[(size_t)s2 * D + col]);
        float4 v3 = *reinterpret_cast<const float4*>(&g_t[(size_t)s3 * D + col]);
        ax += v0.x + v1.x + v2.x + v3.x;
        ay += v0.y + v1.y + v2.y + v3.y;
        az += v0.z + v1.z + v2.z + v3.z;
        aw += v0.w + v1.w + v2.w + v3.w;
    }
    for (; e < end; e++) {
        int s0 = g_csrc[e];
        float4 v0 = *reinterpret_cast<const float4*>(&g_t[(size_t)s0 * D + col]);
        ax += v0.x; ay += v0.y; az += v0.z; aw += v0.w;
    }
    float inv = 1.0f / fmaxf((float)(end - beg), 1.0f);
    ax *= inv; ay *= inv; az *= inv; aw *= inv;
    float p = ax * ax + ay * ay + az * az + aw * aw;
#pragma unroll
    for (int off = 16; off; off >>= 1) p += __shfl_xor_sync(0xffffffffu, p, off);
    float s = chain_epl(sqrtf(p));
    float4 o = make_float4(ax * s, ay * s, az * s, aw * s);
    *reinterpret_cast<float4*>(&out[(size_t)w * D + col]) = o;
}

// ---------------- GEMM + fused hyperbolic epilogue --------------------------
// out[m][j] = scale(||u_m||) * u_m[j],  u = V @ W^T + b
// mode 0: scale = exp0->proj->log0 composite (tangent output)
// mode 1: scale = exp0->proj                 (ball-point output, final layer)
#define KC 64
#define AS 132

__global__ __launch_bounds__(256) void gemm_hyp_kernel(
    const float* __restrict__ V, const float* __restrict__ W,
    const float* __restrict__ bias, float* __restrict__ out,
    int N, int mode)
{
    extern __shared__ float smem[];
    float* Ast    = smem;
    float* Wts    = Ast + KC * AS;
    float* bias_s = Wts + KC * AS;
    float* red    = bias_s + D;
    float* scl    = red + D * 17;

    int tid = threadIdx.x;
    int tx = tid & 15, ty = tid >> 4;
    int m0 = blockIdx.x * 128;

    if (tid < D) bias_s[tid] = bias[tid];

    float acc[8][8];
#pragma unroll
    for (int i = 0; i < 8; i++)
#pragma unroll
        for (int j = 0; j < 8; j++) acc[i][j] = 0.0f;

    for (int kc = 0; kc < D; kc += KC) {
        __syncthreads();
#pragma unroll
        for (int i = 0; i < 8; i++) {
            int idx = tid + i * 256;
            int row = idx >> 4;
            int k4  = idx & 15;
            float4 val = make_float4(0.f, 0.f, 0.f, 0.f);
            int gm = m0 + row;
            if (gm < N) val = *reinterpret_cast<const float4*>(&V[(size_t)gm * D + kc + k4 * 4]);
            int kk = k4 * 4;
            Ast[(kk + 0) * AS + row] = val.x;
            Ast[(kk + 1) * AS + row] = val.y;
            Ast[(kk + 2) * AS + row] = val.z;
            Ast[(kk + 3) * AS + row] = val.w;
        }
#pragma unroll
        for (int i = 0; i < 8; i++) {
            int idx = tid + i * 256;
            int j  = idx >> 4;
            int k4 = idx & 15;
            float4 val = *reinterpret_cast<const float4*>(&W[(size_t)j * D + kc + k4 * 4]);
            int kk = k4 * 4;
            Wts[(kk + 0) * AS + j] = val.x;
            Wts[(kk + 1) * AS + j] = val.y;
            Wts[(kk + 2) * AS + j] = val.z;
            Wts[(kk + 3) * AS + j] = val.w;
        }
        __syncthreads();
#pragma unroll 8
        for (int k = 0; k < KC; k++) {
            float4 a0 = *reinterpret_cast<float4*>(&Ast[k * AS + tx * 4]);
            float4 a1 = *reinterpret_cast<float4*>(&Ast[k * AS + 64 + tx * 4]);
            float4 b0 = *reinterpret_cast<float4*>(&Wts[k * AS + ty * 4]);
            float4 b1 = *reinterpret_cast<float4*>(&Wts[k * AS + 64 + ty * 4]);
            float af[8] = {a0.x, a0.y, a0.z, a0.w, a1.x, a1.y, a1.z, a1.w};
            float bf[8] = {b0.x, b0.y, b0.z, b0.w, b1.x, b1.y, b1.z, b1.w};
#pragma unroll
            for (int i = 0; i < 8; i++)
#pragma unroll
                for (int j = 0; j < 8; j++) acc[i][j] += af[i] * bf[j];
        }
    }

    int rows[8], cols[8];
#pragma unroll
    for (int i = 0; i < 4; i++) { rows[i] = tx * 4 + i; rows[i + 4] = 64 + tx * 4 + i; }
#pragma unroll
    for (int j = 0; j < 4; j++) { cols[j] = ty * 4 + j; cols[j + 4] = 64 + ty * 4 + j; }

#pragma unroll
    for (int i = 0; i < 8; i++) {
        float p = 0.0f;
#pragma unroll
        for (int j = 0; j < 8; j++) {
            float u = acc[i][j] + bias_s[cols[j]];
            acc[i][j] = u;
            p += u * u;
        }
        red[rows[i] * 17 + ty] = p;
    }
    __syncthreads();
    if (tid < D) {
        float s = 0.0f;
#pragma unroll
        for (int t = 0; t < 16; t++) s += red[tid * 17 + t];
        float n = sqrtf(s);
        scl[tid] = (mode == 0) ? chain_epl(n) : chain_ep(n);
    }
    __syncthreads();
#pragma unroll
    for (int i = 0; i < 8; i++) {
        int gm = m0 + rows[i];
        if (gm >= N) continue;
        float s = scl[rows[i]];
        float4 o0 = make_float4(acc[i][0] * s, acc[i][1] * s, acc[i][2] * s, acc[i][3] * s);
        float4 o1 = make_float4(acc[i][4] * s, acc[i][5] * s, acc[i][6] * s, acc[i][7] * s);
        *reinterpret_cast<float4*>(&out[(size_t)gm * D + ty * 4])      = o0;
        *reinterpret_cast<float4*>(&out[(size_t)gm * D + 64 + ty * 4]) = o1;
    }
}

// ---------------- host ------------------------------------------------------
extern "C" void kernel_launch(void* const* d_in, const int* in_sizes, int n_in,
                              void* d_out, int out_size)
{
    const float* x     = (const float*)d_in[0];
    const int*   ei    = (const int*)d_in[1];
    const float* msg_W = (const float*)d_in[2];
    const float* msg_b = (const float*)d_in[3];
    const float* upd_W = (const float*)d_in[4];
    const float* upd_b = (const float*)d_in[5];
    float* outp = (float*)d_out;

    int N = in_sizes[0] / D;
    int E = in_sizes[1] / 2;
    int L = in_sizes[3] / D;
    if (N > MAXN || E > MAXE) return;

    const int* src = ei;
    const int* dst = ei + E;

    float *p_v, *p_t, *p_h;
    int *p_deg;
    cudaGetSymbolAddress((void**)&p_v,   g_v);
    cudaGetSymbolAddress((void**)&p_t,   g_t);
    cudaGetSymbolAddress((void**)&p_h,   g_h);
    cudaGetSymbolAddress((void**)&p_deg, g_deg);

    static bool attr_done = false;
    const int SMEM = (KC * AS * 2 + D + D * 17 + D) * sizeof(float);
    if (!attr_done) {
        cudaFuncSetAttribute(gemm_hyp_kernel, cudaFuncAttributeMaxDynamicSharedMemorySize, SMEM);
        attr_done = true;
    }

    // ---- CSR build (edge structure only; shared by all layers) ----
    zero_int_kernel<<<(N + 255) / 256, 256>>>(p_deg, N);
    hist_kernel<<<(E + 255) / 256, 256>>>(dst, E);
    scan_kernel<<<1, 1024>>>(N);
    fill_kernel<<<(E + 255) / 256, 256>>>(src, dst, E);

    int gemm_blocks  = (N + 127) / 128;
    int warp_blocksN = (N * 32 + 255) / 256;

    // layer 0 input tangent
    prep_log0_kernel<<<warp_blocksN, 256>>>(x, p_v, N);

    const float* v_in = p_v;
    for (int l = 0; l < L; l++) {
        // message hyp_linear -> tangent messages t
        gemm_hyp_kernel<<<gemm_blocks, 256, SMEM>>>(v_in, msg_W + (size_t)l * D * D,
                                                    msg_b + (size_t)l * D, p_t, N, 0);
        // fused gather + mean + exp0/proj/log0 -> tangent v
        agg_kernel<<<warp_blocksN, 256>>>(p_v, N);
        // update hyp_linear; interior layers emit tangent of next layer directly
        if (l == L - 1) {
            gemm_hyp_kernel<<<gemm_blocks, 256, SMEM>>>(p_v, upd_W + (size_t)l * D * D,
                                                        upd_b + (size_t)l * D, outp, N, 1);
        } else {
            gemm_hyp_kernel<<<gemm_blocks, 256, SMEM>>>(p_v, upd_W + (size_t)l * D * D,
                                                        upd_b + (size_t)l * D, p_h, N, 0);
            v_in = p_h;
        }
    }
}

// round 3
// speedup vs baseline: 2.5920x; 1.2447x over previous
#include <cuda_runtime.h>
#include <math.h>
#include <stdint.h>

#define EPS 1e-5f
#define MAX_NORM 0.95f
#define D 128
#define MAXN 50000
#define MAXE 800000

// ---------------- scratch (static device globals) ---------------------------
__device__ float g_v[MAXN * D];    // tangent vectors (GEMM input)
__device__ float g_t[MAXN * D];    // message tangents (gather source)
__device__ float g_h[MAXN * D];    // inter-layer tangent state
__device__ int   g_deg[MAXN];      // in-degree
__device__ int   g_off[MAXN + 1];  // CSR offsets
__device__ int   g_cur[MAXN];      // CSR fill cursors
__device__ int   g_csrc[MAXE];     // CSR src ids grouped by dst

// ---------------- scalar chains ---------------------------------------------
__device__ __forceinline__ float s_log0(float n) {
    float nm  = fmaxf(n, EPS);
    float arg = fminf(nm, 1.0f - EPS);
    return atanhf(arg) / nm;
}
__device__ __forceinline__ float chain_epl(float n) {
    float nm = fmaxf(n, EPS);
    float a  = tanhf(nm) / nm;
    float na = n * a;
    float b  = (na > MAX_NORM) ? MAX_NORM / fmaxf(na, EPS) : 1.0f;
    float nb = na * b;
    float nbm = fmaxf(nb, EPS);
    float arg = fminf(nbm, 1.0f - EPS);
    float c  = atanhf(arg) / nbm;
    return a * b * c;
}
__device__ __forceinline__ float chain_ep(float n) {
    float nm = fmaxf(n, EPS);
    float a  = tanhf(nm) / nm;
    float na = n * a;
    float b  = (na > MAX_NORM) ? MAX_NORM / fmaxf(na, EPS) : 1.0f;
    return a * b;
}

// ---------------- tf32 helpers ----------------------------------------------
__device__ __forceinline__ uint32_t f2tf32(float x) {
    uint32_t r;
    asm("cvt.rna.tf32.f32 %0, %1;" : "=r"(r) : "f"(x));
    return r;
}
__device__ __forceinline__ void split_tf32(float x, uint32_t& hi, uint32_t& lo) {
    hi = f2tf32(x);
    float hif = __uint_as_float(hi);
    lo = f2tf32(x - hif);
}
__device__ __forceinline__ void mma_tf32(float* d, uint32_t a0, uint32_t a1,
                                         uint32_t a2, uint32_t a3,
                                         uint32_t b0, uint32_t b1) {
    asm volatile(
        "mma.sync.aligned.m16n8k8.row.col.f32.tf32.tf32.f32 "
        "{%0,%1,%2,%3}, {%4,%5,%6,%7}, {%8,%9}, {%0,%1,%2,%3};\n"
        : "+f"(d[0]), "+f"(d[1]), "+f"(d[2]), "+f"(d[3])
        : "r"(a0), "r"(a1), "r"(a2), "r"(a3), "r"(b0), "r"(b1));
}

// ---------------- CSR construction ------------------------------------------
__global__ void zero_int_kernel(int* __restrict__ p, int n) {
    int i = blockIdx.x * blockDim.x + threadIdx.x;
    if (i < n) p[i] = 0;
}
__global__ void hist_kernel(const int* __restrict__ dst, int E) {
    int e = blockIdx.x * blockDim.x + threadIdx.x;
    if (e < E) atomicAdd(&g_deg[dst[e]], 1);
}
__global__ void scan_kernel(int N) {
    int lane = threadIdx.x & 31, wid = threadIdx.x >> 5;
    __shared__ int wsum[32];
    __shared__ int running;
    if (threadIdx.x == 0) running = 0;
    __syncthreads();
    for (int base = 0; base < N; base += 1024) {
        int i = base + (int)threadIdx.x;
        int v = (i < N) ? g_deg[i] : 0;
        int x = v;
#pragma unroll
        for (int o = 1; o < 32; o <<= 1) {
            int y = __shfl_up_sync(0xffffffffu, x, o);
            if (lane >= o) x += y;
        }
        if (lane == 31) wsum[wid] = x;
        __syncthreads();
        if (wid == 0) {
            int s = wsum[lane];
#pragma unroll
            for (int o = 1; o < 32; o <<= 1) {
                int y = __shfl_up_sync(0xffffffffu, s, o);
                if (lane >= o) s += y;
            }
            wsum[lane] = s;
        }
        __syncthreads();
        int warp_prefix = (wid == 0) ? 0 : wsum[wid - 1];
        int excl = running + warp_prefix + (x - v);
        if (i < N) { g_off[i] = excl; g_cur[i] = excl; }
        int tile_total = wsum[31];
        __syncthreads();
        if (threadIdx.x == 0) running += tile_total;
        __syncthreads();
    }
    if (threadIdx.x == 0) g_off[N] = running;
}
__global__ void fill_kernel(const int* __restrict__ src, const int* __restrict__ dst, int E) {
    int e = blockIdx.x * blockDim.x + threadIdx.x;
    if (e < E) {
        int p = atomicAdd(&g_cur[dst[e]], 1);
        g_csrc[p] = src[e];
    }
}

// ---------------- prep: v = log0(x) -----------------------------------------
__global__ void prep_log0_kernel(const float* __restrict__ in, float* __restrict__ out, int N) {
    int w    = (blockIdx.x * blockDim.x + threadIdx.x) >> 5;
    int lane = threadIdx.x & 31;
    if (w >= N) return;
    float4 v = *reinterpret_cast<const float4*>(&in[(size_t)w * D + lane * 4]);
    float p = v.x * v.x + v.y * v.y + v.z * v.z + v.w * v.w;
#pragma unroll
    for (int off = 16; off; off >>= 1) p += __shfl_xor_sync(0xffffffffu, p, off);
    float s = s_log0(sqrtf(p));
    v.x *= s; v.y *= s; v.z *= s; v.w *= s;
    *reinterpret_cast<float4*>(&out[(size_t)w * D + lane * 4]) = v;
}

// ---------------- fused gather + mean + chain_epl ---------------------------
__global__ void agg_kernel(float* __restrict__ out, int N) {
    int w    = (blockIdx.x * blockDim.x + threadIdx.x) >> 5;
    int lane = threadIdx.x & 31;
    if (w >= N) return;
    int beg = g_off[w], end = g_off[w + 1];
    float ax = 0.f, ay = 0.f, az = 0.f, aw = 0.f;
    int e = beg;
    int col = lane * 4;
    for (; e + 4 <= end; e += 4) {
        int s0 = g_csrc[e], s1 = g_csrc[e + 1], s2 = g_csrc[e + 2], s3 = g_csrc[e + 3];
        float4 v0 = *reinterpret_cast<const float4*>(&g_t[(size_t)s0 * D + col]);
        float4 v1 = *reinterpret_cast<const float4*>(&g_t[(size_t)s1 * D + col]);
        float4 v2 = *reinterpret_cast<const float4*>(&g_t[(size_t)s2 * D + col]);
        float4 v3 = *reinterpret_cast<const float4*>(&g_t[(size_t)s3 * D + col]);
        ax += v0.x + v1.x + v2.x + v3.x;
        ay += v0.y + v1.y + v2.y + v3.y;
        az += v0.z + v1.z + v2.z + v3.z;
        aw += v0.w + v1.w + v2.w + v3.w;
    }
    for (; e < end; e++) {
        int s0 = g_csrc[e];
        float4 v0 = *reinterpret_cast<const float4*>(&g_t[(size_t)s0 * D + col]);
        ax += v0.x; ay += v0.y; az += v0.z; aw += v0.w;
    }
    float inv = 1.0f / fmaxf((float)(end - beg), 1.0f);
    ax *= inv; ay *= inv; az *= inv; aw *= inv;
    float p = ax * ax + ay * ay + az * az + aw * aw;
#pragma unroll
    for (int off = 16; off; off >>= 1) p += __shfl_xor_sync(0xffffffffu, p, off);
    float s = chain_epl(sqrtf(p));
    float4 o = make_float4(ax * s, ay * s, az * s, aw * s);
    *reinterpret_cast<float4*>(&out[(size_t)w * D + col]) = o;
}

// ---------------- 3xTF32 tensor-core GEMM + fused hyperbolic epilogue -------
// out[m][j] = scale(||u_m||) * u_m[j],  u = V @ W^T + b
// CTA: 128 rows x 128 cols output, K=128 fully resident in smem.
// 8 warps: warp tile 32 rows x 64 cols via m16n8k8 fragments.
#define AS 132   // padded smem row stride (floats); 132*4B = 16B-aligned rows

__global__ __launch_bounds__(256) void gemm_hyp_tc_kernel(
    const float* __restrict__ V, const float* __restrict__ W,
    const float* __restrict__ bias, float* __restrict__ out,
    int N, int mode)
{
    extern __shared__ float smem[];
    float* As     = smem;                          // [128][AS] fp32 A tile
    uint32_t* Whi = (uint32_t*)(As + 128 * AS);    // [128][AS] tf32 hi
    uint32_t* Wlo = Whi + 128 * AS;                // [128][AS] tf32 lo
    float* bias_s = (float*)(Wlo + 128 * AS);      // [128]
    float* red    = bias_s + 128;                  // [128][2]
    float* scl    = red + 256;                     // [128]

    int tid  = threadIdx.x;
    int lane = tid & 31;
    int warp = tid >> 5;
    int rbase = (warp >> 1) * 32;   // 4 row groups
    int cbase = (warp & 1) * 64;    // 2 col groups
    int m0 = blockIdx.x * 128;

    if (tid < 128) bias_s[tid] = bias[tid];

    // ---- load A tile (fp32) and W tile (pre-split hi/lo) ----
#pragma unroll
    for (int i = 0; i < 16; i++) {
        int idx = tid + i * 256;            // 4096 float4 slots
        int row = idx >> 5;
        int c4  = (idx & 31) * 4;
        float4 av = make_float4(0.f, 0.f, 0.f, 0.f);
        int gm = m0 + row;
        if (gm < N) av = *reinterpret_cast<const float4*>(&V[(size_t)gm * D + c4]);
        *reinterpret_cast<float4*>(&As[row * AS + c4]) = av;

        float4 wv = *reinterpret_cast<const float4*>(&W[(size_t)row * D + c4]);
        uint32_t h0, l0, h1, l1, h2, l2, h3, l3;
        split_tf32(wv.x, h0, l0); split_tf32(wv.y, h1, l1);
        split_tf32(wv.z, h2, l2); split_tf32(wv.w, h3, l3);
        uint32_t* ph = &Whi[row * AS + c4];
        uint32_t* pl = &Wlo[row * AS + c4];
        ph[0] = h0; ph[1] = h1; ph[2] = h2; ph[3] = h3;
        pl[0] = l0; pl[1] = l1; pl[2] = l2; pl[3] = l3;
    }
    __syncthreads();

    float acc[2][8][4];
#pragma unroll
    for (int rt = 0; rt < 2; rt++)
#pragma unroll
        for (int ct = 0; ct < 8; ct++)
#pragma unroll
            for (int q = 0; q < 4; q++) acc[rt][ct][q] = 0.0f;

    int c = lane & 3;
    int g = lane >> 2;

#pragma unroll 4
    for (int ks = 0; ks < 16; ks++) {
        int k0 = ks * 8;
        // A fragments for 2 row tiles, split to hi/lo on the fly
        uint32_t ahi[2][4], alo[2][4];
#pragma unroll
        for (int rt = 0; rt < 2; rt++) {
            int r0 = rbase + rt * 16 + g;
            float a0 = As[r0 * AS + k0 + c];
            float a1 = As[(r0 + 8) * AS + k0 + c];
            float a2 = As[r0 * AS + k0 + 4 + c];
            float a3 = As[(r0 + 8) * AS + k0 + 4 + c];
            split_tf32(a0, ahi[rt][0], alo[rt][0]);
            split_tf32(a1, ahi[rt][1], alo[rt][1]);
            split_tf32(a2, ahi[rt][2], alo[rt][2]);
            split_tf32(a3, ahi[rt][3], alo[rt][3]);
        }
#pragma unroll
        for (int ct = 0; ct < 8; ct++) {
            int col = cbase + ct * 8 + g;
            uint32_t bh0 = Whi[col * AS + k0 + c];
            uint32_t bh1 = Whi[col * AS + k0 + 4 + c];
            uint32_t bl0 = Wlo[col * AS + k0 + c];
            uint32_t bl1 = Wlo[col * AS + k0 + 4 + c];
#pragma unroll
            for (int rt = 0; rt < 2; rt++) {
                mma_tf32(acc[rt][ct], ahi[rt][0], ahi[rt][1], ahi[rt][2], ahi[rt][3], bh0, bh1);
                mma_tf32(acc[rt][ct], ahi[rt][0], ahi[rt][1], ahi[rt][2], ahi[rt][3], bl0, bl1);
                mma_tf32(acc[rt][ct], alo[rt][0], alo[rt][1], alo[rt][2], alo[rt][3], bh0, bh1);
            }
        }
    }

    // ---- epilogue: bias add + per-row sumsq ----
    // thread holds rows {rbase+rt*16+g, +8}, cols cbase+ct*8+2c+{0,1}
    float prow[2][2];  // [rt][row half] partial sumsq over this thread's 16 cols
#pragma unroll
    for (int rt = 0; rt < 2; rt++) {
        prow[rt][0] = 0.f; prow[rt][1] = 0.f;
#pragma unroll
        for (int ct = 0; ct < 8; ct++) {
            int colb = cbase + ct * 8 + 2 * c;
            float u0 = acc[rt][ct][0] + bias_s[colb];
            float u1 = acc[rt][ct][1] + bias_s[colb + 1];
            float u2 = acc[rt][ct][2] + bias_s[colb];
            float u3 = acc[rt][ct][3] + bias_s[colb + 1];
            acc[rt][ct][0] = u0; acc[rt][ct][1] = u1;
            acc[rt][ct][2] = u2; acc[rt][ct][3] = u3;
            prow[rt][0] += u0 * u0 + u1 * u1;
            prow[rt][1] += u2 * u2 + u3 * u3;
        }
        // reduce across the 4 threads sharing these rows (lane&3 varies)
#pragma unroll
        for (int o = 1; o < 4; o <<= 1) {
            prow[rt][0] += __shfl_xor_sync(0xffffffffu, prow[rt][0], o);
            prow[rt][1] += __shfl_xor_sync(0xffffffffu, prow[rt][1], o);
        }
    }
    int cg = warp & 1;
    if (c == 0) {
#pragma unroll
        for (int rt = 0; rt < 2; rt++) {
            int r0 = rbase + rt * 16 + g;
            red[r0 * 2 + cg]       = prow[rt][0];
            red[(r0 + 8) * 2 + cg] = prow[rt][1];
        }
    }
    __syncthreads();
    if (tid < 128) {
        float s = red[tid * 2] + red[tid * 2 + 1];
        float n = sqrtf(s);
        scl[tid] = (mode == 0) ? chain_epl(n) : chain_ep(n);
    }
    __syncthreads();

    // ---- scaled store ----
#pragma unroll
    for (int rt = 0; rt < 2; rt++) {
        int r0 = rbase + rt * 16 + g;
        float s0 = scl[r0];
        float s1 = scl[r0 + 8];
        int gm0 = m0 + r0;
        int gm1 = gm0 + 8;
#pragma unroll
        for (int ct = 0; ct < 8; ct++) {
            int colb = cbase + ct * 8 + 2 * c;
            if (gm0 < N) {
                float2 o = make_float2(acc[rt][ct][0] * s0, acc[rt][ct][1] * s0);
                *reinterpret_cast<float2*>(&out[(size_t)gm0 * D + colb]) = o;
            }
            if (gm1 < N) {
                float2 o = make_float2(acc[rt][ct][2] * s1, acc[rt][ct][3] * s1);
                *reinterpret_cast<float2*>(&out[(size_t)gm1 * D + colb]) = o;
            }
        }
    }
}

// ---------------- host ------------------------------------------------------
extern "C" void kernel_launch(void* const* d_in, const int* in_sizes, int n_in,
                              void* d_out, int out_size)
{
    const float* x     = (const float*)d_in[0];
    const int*   ei    = (const int*)d_in[1];
    const float* msg_W = (const float*)d_in[2];
    const float* msg_b = (const float*)d_in[3];
    const float* upd_W = (const float*)d_in[4];
    const float* upd_b = (const float*)d_in[5];
    float* outp = (float*)d_out;

    int N = in_sizes[0] / D;
    int E = in_sizes[1] / 2;
    int L = in_sizes[3] / D;
    if (N > MAXN || E > MAXE) return;

    const int* src = ei;
    const int* dst = ei + E;

    float *p_v, *p_t, *p_h;
    int *p_deg;
    cudaGetSymbolAddress((void**)&p_v,   g_v);
    cudaGetSymbolAddress((void**)&p_t,   g_t);
    cudaGetSymbolAddress((void**)&p_h,   g_h);
    cudaGetSymbolAddress((void**)&p_deg, g_deg);

    // smem: As + Whi + Wlo (3 * 128*AS words) + bias(128) + red(256) + scl(128)
    const int SMEM = (3 * 128 * AS + 128 + 256 + 128) * (int)sizeof(float);
    static bool attr_done = false;
    if (!attr_done) {
        cudaFuncSetAttribute(gemm_hyp_tc_kernel,
                             cudaFuncAttributeMaxDynamicSharedMemorySize, SMEM);
        attr_done = true;
    }

    // ---- CSR build (edge structure only; shared by all layers) ----
    zero_int_kernel<<<(N + 255) / 256, 256>>>(p_deg, N);
    hist_kernel<<<(E + 255) / 256, 256>>>(dst, E);
    scan_kernel<<<1, 1024>>>(N);
    fill_kernel<<<(E + 255) / 256, 256>>>(src, dst, E);

    int gemm_blocks  = (N + 127) / 128;
    int warp_blocksN = (N * 32 + 255) / 256;

    prep_log0_kernel<<<warp_blocksN, 256>>>(x, p_v, N);

    const float* v_in = p_v;
    for (int l = 0; l < L; l++) {
        gemm_hyp_tc_kernel<<<gemm_blocks, 256, SMEM>>>(v_in, msg_W + (size_t)l * D * D,
                                                       msg_b + (size_t)l * D, p_t, N, 0);
        agg_kernel<<<warp_blocksN, 256>>>(p_v, N);
        if (l == L - 1) {
            gemm_hyp_tc_kernel<<<gemm_blocks, 256, SMEM>>>(p_v, upd_W + (size_t)l * D * D,
                                                           upd_b + (size_t)l * D, outp, N, 1);
        } else {
            gemm_hyp_tc_kernel<<<gemm_blocks, 256, SMEM>>>(p_v, upd_W + (size_t)l * D * D,
                                                           upd_b + (size_t)l * D, p_h, N, 0);
            v_in = p_h;
        }
    }
}

// round 4
// speedup vs baseline: 2.9118x; 1.1234x over previous
#include <cuda_runtime.h>
#include <cuda_fp16.h>
#include <math.h>
#include <stdint.h>

#define EPS 1e-5f
#define MAX_NORM 0.95f
#define D 128
#define MAXN 50000
#define MAXE 800000

// ---------------- scratch (static device globals) ---------------------------
__device__ float  g_v[MAXN * D];     // tangent vectors (GEMM input)
__device__ __half g_t16[MAXN * D];   // fp16 message tangents (gather source)
__device__ float  g_h[MAXN * D];     // inter-layer tangent state (fp32)
__device__ int    g_deg[MAXN];
__device__ int    g_off[MAXN + 1];
__device__ int    g_cur[MAXN];
__device__ int    g_csrc[MAXE];

// ---------------- scalar chains ---------------------------------------------
__device__ __forceinline__ float s_log0(float n) {
    float nm  = fmaxf(n, EPS);
    float arg = fminf(nm, 1.0f - EPS);
    return atanhf(arg) / nm;
}
__device__ __forceinline__ float chain_epl(float n) {
    float nm = fmaxf(n, EPS);
    float a  = tanhf(nm) / nm;
    float na = n * a;
    float b  = (na > MAX_NORM) ? MAX_NORM / fmaxf(na, EPS) : 1.0f;
    float nb = na * b;
    float nbm = fmaxf(nb, EPS);
    float arg = fminf(nbm, 1.0f - EPS);
    float c  = atanhf(arg) / nbm;
    return a * b * c;
}
__device__ __forceinline__ float chain_ep(float n) {
    float nm = fmaxf(n, EPS);
    float a  = tanhf(nm) / nm;
    float na = n * a;
    float b  = (na > MAX_NORM) ? MAX_NORM / fmaxf(na, EPS) : 1.0f;
    return a * b;
}

// ---------------- tf32 helpers ----------------------------------------------
__device__ __forceinline__ uint32_t f2tf32(float x) {
    uint32_t r;
    asm("cvt.rna.tf32.f32 %0, %1;" : "=r"(r) : "f"(x));
    return r;
}
__device__ __forceinline__ void split_tf32(float x, uint32_t& hi, uint32_t& lo) {
    hi = f2tf32(x);
    float hif = __uint_as_float(hi);
    lo = f2tf32(x - hif);
}
__device__ __forceinline__ void mma_tf32(float* d, uint32_t a0, uint32_t a1,
                                         uint32_t a2, uint32_t a3,
                                         uint32_t b0, uint32_t b1) {
    asm volatile(
        "mma.sync.aligned.m16n8k8.row.col.f32.tf32.tf32.f32 "
        "{%0,%1,%2,%3}, {%4,%5,%6,%7}, {%8,%9}, {%0,%1,%2,%3};\n"
        : "+f"(d[0]), "+f"(d[1]), "+f"(d[2]), "+f"(d[3])
        : "r"(a0), "r"(a1), "r"(a2), "r"(a3), "r"(b0), "r"(b1));
}

// ---------------- CSR construction ------------------------------------------
__global__ void zero_int_kernel(int* __restrict__ p, int n) {
    int i = blockIdx.x * blockDim.x + threadIdx.x;
    if (i < n) p[i] = 0;
}
__global__ void hist_kernel(const int* __restrict__ dst, int E) {
    int e = blockIdx.x * blockDim.x + threadIdx.x;
    if (e < E) atomicAdd(&g_deg[dst[e]], 1);
}
__global__ void scan_kernel(int N) {
    int lane = threadIdx.x & 31, wid = threadIdx.x >> 5;
    __shared__ int wsum[32];
    __shared__ int running;
    if (threadIdx.x == 0) running = 0;
    __syncthreads();
    for (int base = 0; base < N; base += 1024) {
        int i = base + (int)threadIdx.x;
        int v = (i < N) ? g_deg[i] : 0;
        int x = v;
#pragma unroll
        for (int o = 1; o < 32; o <<= 1) {
            int y = __shfl_up_sync(0xffffffffu, x, o);
            if (lane >= o) x += y;
        }
        if (lane == 31) wsum[wid] = x;
        __syncthreads();
        if (wid == 0) {
            int s = wsum[lane];
#pragma unroll
            for (int o = 1; o < 32; o <<= 1) {
                int y = __shfl_up_sync(0xffffffffu, s, o);
                if (lane >= o) s += y;
            }
            wsum[lane] = s;
        }
        __syncthreads();
        int warp_prefix = (wid == 0) ? 0 : wsum[wid - 1];
        int excl = running + warp_prefix + (x - v);
        if (i < N) { g_off[i] = excl; g_cur[i] = excl; }
        int tile_total = wsum[31];
        __syncthreads();
        if (threadIdx.x == 0) running += tile_total;
        __syncthreads();
    }
    if (threadIdx.x == 0) g_off[N] = running;
}
__global__ void fill_kernel(const int* __restrict__ src, const int* __restrict__ dst, int E) {
    int e = blockIdx.x * blockDim.x + threadIdx.x;
    if (e < E) {
        int p = atomicAdd(&g_cur[dst[e]], 1);
        g_csrc[p] = src[e];
    }
}

// ---------------- prep: v = log0(x) -----------------------------------------
__global__ void prep_log0_kernel(const float* __restrict__ in, float* __restrict__ out, int N) {
    int w    = (blockIdx.x * blockDim.x + threadIdx.x) >> 5;
    int lane = threadIdx.x & 31;
    if (w >= N) return;
    float4 v = *reinterpret_cast<const float4*>(&in[(size_t)w * D + lane * 4]);
    float p = v.x * v.x + v.y * v.y + v.z * v.z + v.w * v.w;
#pragma unroll
    for (int off = 16; off; off >>= 1) p += __shfl_xor_sync(0xffffffffu, p, off);
    float s = s_log0(sqrtf(p));
    v.x *= s; v.y *= s; v.z *= s; v.w *= s;
    *reinterpret_cast<float4*>(&out[(size_t)w * D + lane * 4]) = v;
}

// ---------------- fused gather(fp16) + mean + chain_epl ---------------------
__global__ void agg_kernel(float* __restrict__ out, int N) {
    int w    = (blockIdx.x * blockDim.x + threadIdx.x) >> 5;
    int lane = threadIdx.x & 31;
    if (w >= N) return;
    int beg = g_off[w], end = g_off[w + 1];
    float ax = 0.f, ay = 0.f, az = 0.f, aw = 0.f;
    int e = beg;
    int col = lane * 4;
#pragma unroll 1
    for (; e + 4 <= end; e += 4) {
        int s0 = g_csrc[e], s1 = g_csrc[e + 1], s2 = g_csrc[e + 2], s3 = g_csrc[e + 3];
        uint2 u0 = *reinterpret_cast<const uint2*>(&g_t16[(size_t)s0 * D + col]);
        uint2 u1 = *reinterpret_cast<const uint2*>(&g_t16[(size_t)s1 * D + col]);
        uint2 u2 = *reinterpret_cast<const uint2*>(&g_t16[(size_t)s2 * D + col]);
        uint2 u3 = *reinterpret_cast<const uint2*>(&g_t16[(size_t)s3 * D + col]);
        float2 a, b;
        a = __half22float2(*(__half2*)&u0.x); b = __half22float2(*(__half2*)&u0.y);
        ax += a.x; ay += a.y; az += b.x; aw += b.y;
        a = __half22float2(*(__half2*)&u1.x); b = __half22float2(*(__half2*)&u1.y);
        ax += a.x; ay += a.y; az += b.x; aw += b.y;
        a = __half22float2(*(__half2*)&u2.x); b = __half22float2(*(__half2*)&u2.y);
        ax += a.x; ay += a.y; az += b.x; aw += b.y;
        a = __half22float2(*(__half2*)&u3.x); b = __half22float2(*(__half2*)&u3.y);
        ax += a.x; ay += a.y; az += b.x; aw += b.y;
    }
    for (; e < end; e++) {
        int s0 = g_csrc[e];
        uint2 u0 = *reinterpret_cast<const uint2*>(&g_t16[(size_t)s0 * D + col]);
        float2 a = __half22float2(*(__half2*)&u0.x);
        float2 b = __half22float2(*(__half2*)&u0.y);
        ax += a.x; ay += a.y; az += b.x; aw += b.y;
    }
    float inv = 1.0f / fmaxf((float)(end - beg), 1.0f);
    ax *= inv; ay *= inv; az *= inv; aw *= inv;
    float p = ax * ax + ay * ay + az * az + aw * aw;
#pragma unroll
    for (int off = 16; off; off >>= 1) p += __shfl_xor_sync(0xffffffffu, p, off);
    float s = chain_epl(sqrtf(p));
    float4 o = make_float4(ax * s, ay * s, az * s, aw * s);
    *reinterpret_cast<float4*>(&out[(size_t)w * D + col]) = o;
}

// ---------------- 3xTF32 tensor-core GEMM + fused hyperbolic epilogue -------
// CTA: 128x128 output tile, K=128 resident. 16 warps, warp tile 32x32.
// mode 0: chain_epl, fp16 store to out16 (message tangents)
// mode 1: chain_ep,  fp32 store (final ball-point output)
// mode 2: chain_epl, fp32 store (inter-layer tangent)
#define AS 132

__global__ __launch_bounds__(512) void gemm_hyp_tc_kernel(
    const float* __restrict__ V, const float* __restrict__ W,
    const float* __restrict__ bias, float* __restrict__ out,
    __half* __restrict__ out16, int N, int mode)
{
    extern __shared__ float smem[];
    float* As     = smem;                          // [128][AS] fp32 A tile
    uint32_t* Whi = (uint32_t*)(As + 128 * AS);    // [128][AS] tf32 hi (col-major rows=col)
    uint32_t* Wlo = Whi + 128 * AS;                // [128][AS] tf32 lo
    float* bias_s = (float*)(Wlo + 128 * AS);      // [128]
    float* red    = bias_s + 128;                  // [128][4]
    float* scl    = red + 512;                     // [128]

    int tid  = threadIdx.x;
    int lane = tid & 31;
    int warp = tid >> 5;
    int rbase = (warp >> 2) * 32;   // 4 row groups
    int cbase = (warp & 3) * 32;    // 4 col groups
    int m0 = blockIdx.x * 128;

    if (tid < 128) bias_s[tid] = bias[tid];

    // ---- load A tile (fp32) and W tile (pre-split hi/lo) ----
#pragma unroll
    for (int i = 0; i < 8; i++) {
        int idx = tid + i * 512;            // 4096 float4 slots
        int row = idx >> 5;
        int c4  = (idx & 31) * 4;
        float4 av = make_float4(0.f, 0.f, 0.f, 0.f);
        int gm = m0 + row;
        if (gm < N) av = *reinterpret_cast<const float4*>(&V[(size_t)gm * D + c4]);
        *reinterpret_cast<float4*>(&As[row * AS + c4]) = av;

        float4 wv = *reinterpret_cast<const float4*>(&W[(size_t)row * D + c4]);
        uint32_t h0, l0, h1, l1, h2, l2, h3, l3;
        split_tf32(wv.x, h0, l0); split_tf32(wv.y, h1, l1);
        split_tf32(wv.z, h2, l2); split_tf32(wv.w, h3, l3);
        uint32_t* ph = &Whi[row * AS + c4];
        uint32_t* pl = &Wlo[row * AS + c4];
        ph[0] = h0; ph[1] = h1; ph[2] = h2; ph[3] = h3;
        pl[0] = l0; pl[1] = l1; pl[2] = l2; pl[3] = l3;
    }
    __syncthreads();

    float acc[2][4][4];
#pragma unroll
    for (int rt = 0; rt < 2; rt++)
#pragma unroll
        for (int ct = 0; ct < 4; ct++)
#pragma unroll
            for (int q = 0; q < 4; q++) acc[rt][ct][q] = 0.0f;

    int c = lane & 3;
    int g = lane >> 2;

#pragma unroll 4
    for (int ks = 0; ks < 16; ks++) {
        int k0 = ks * 8;
        uint32_t ahi[2][4], alo[2][4];
#pragma unroll
        for (int rt = 0; rt < 2; rt++) {
            int r0 = rbase + rt * 16 + g;
            float a0 = As[r0 * AS + k0 + c];
            float a1 = As[(r0 + 8) * AS + k0 + c];
            float a2 = As[r0 * AS + k0 + 4 + c];
            float a3 = As[(r0 + 8) * AS + k0 + 4 + c];
            split_tf32(a0, ahi[rt][0], alo[rt][0]);
            split_tf32(a1, ahi[rt][1], alo[rt][1]);
            split_tf32(a2, ahi[rt][2], alo[rt][2]);
            split_tf32(a3, ahi[rt][3], alo[rt][3]);
        }
#pragma unroll
        for (int ct = 0; ct < 4; ct++) {
            int col = cbase + ct * 8 + g;
            uint32_t bh0 = Whi[col * AS + k0 + c];
            uint32_t bh1 = Whi[col * AS + k0 + 4 + c];
            uint32_t bl0 = Wlo[col * AS + k0 + c];
            uint32_t bl1 = Wlo[col * AS + k0 + 4 + c];
#pragma unroll
            for (int rt = 0; rt < 2; rt++) {
                mma_tf32(acc[rt][ct], ahi[rt][0], ahi[rt][1], ahi[rt][2], ahi[rt][3], bh0, bh1);
                mma_tf32(acc[rt][ct], ahi[rt][0], ahi[rt][1], ahi[rt][2], ahi[rt][3], bl0, bl1);
                mma_tf32(acc[rt][ct], alo[rt][0], alo[rt][1], alo[rt][2], alo[rt][3], bh0, bh1);
            }
        }
    }

    // ---- epilogue: bias add + per-row sumsq ----
    float prow[2][2];
#pragma unroll
    for (int rt = 0; rt < 2; rt++) {
        prow[rt][0] = 0.f; prow[rt][1] = 0.f;
#pragma unroll
        for (int ct = 0; ct < 4; ct++) {
            int colb = cbase + ct * 8 + 2 * c;
            float u0 = acc[rt][ct][0] + bias_s[colb];
            float u1 = acc[rt][ct][1] + bias_s[colb + 1];
            float u2 = acc[rt][ct][2] + bias_s[colb];
            float u3 = acc[rt][ct][3] + bias_s[colb + 1];
            acc[rt][ct][0] = u0; acc[rt][ct][1] = u1;
            acc[rt][ct][2] = u2; acc[rt][ct][3] = u3;
            prow[rt][0] += u0 * u0 + u1 * u1;
            prow[rt][1] += u2 * u2 + u3 * u3;
        }
#pragma unroll
        for (int o = 1; o < 4; o <<= 1) {
            prow[rt][0] += __shfl_xor_sync(0xffffffffu, prow[rt][0], o);
            prow[rt][1] += __shfl_xor_sync(0xffffffffu, prow[rt][1], o);
        }
    }
    int cg = warp & 3;
    if (c == 0) {
#pragma unroll
        for (int rt = 0; rt < 2; rt++) {
            int r0 = rbase + rt * 16 + g;
            red[r0 * 4 + cg]       = prow[rt][0];
            red[(r0 + 8) * 4 + cg] = prow[rt][1];
        }
    }
    __syncthreads();
    if (tid < 128) {
        float s = red[tid * 4] + red[tid * 4 + 1] + red[tid * 4 + 2] + red[tid * 4 + 3];
        float n = sqrtf(s);
        scl[tid] = (mode == 1) ? chain_ep(n) : chain_epl(n);
    }
    __syncthreads();

    // ---- scaled store ----
#pragma unroll
    for (int rt = 0; rt < 2; rt++) {
        int r0 = rbase + rt * 16 + g;
        float s0 = scl[r0];
        float s1 = scl[r0 + 8];
        int gm0 = m0 + r0;
        int gm1 = gm0 + 8;
#pragma unroll
        for (int ct = 0; ct < 4; ct++) {
            int colb = cbase + ct * 8 + 2 * c;
            if (mode == 0) {
                if (gm0 < N) {
                    __half2 hv = __floats2half2_rn(acc[rt][ct][0] * s0, acc[rt][ct][1] * s0);
                    *reinterpret_cast<__half2*>(&out16[(size_t)gm0 * D + colb]) = hv;
                }
                if (gm1 < N) {
                    __half2 hv = __floats2half2_rn(acc[rt][ct][2] * s1, acc[rt][ct][3] * s1);
                    *reinterpret_cast<__half2*>(&out16[(size_t)gm1 * D + colb]) = hv;
                }
            } else {
                if (gm0 < N) {
                    float2 o = make_float2(acc[rt][ct][0] * s0, acc[rt][ct][1] * s0);
                    *reinterpret_cast<float2*>(&out[(size_t)gm0 * D + colb]) = o;
                }
                if (gm1 < N) {
                    float2 o = make_float2(acc[rt][ct][2] * s1, acc[rt][ct][3] * s1);
                    *reinterpret_cast<float2*>(&out[(size_t)gm1 * D + colb]) = o;
                }
            }
        }
    }
}

// ---------------- host ------------------------------------------------------
extern "C" void kernel_launch(void* const* d_in, const int* in_sizes, int n_in,
                              void* d_out, int out_size)
{
    const float* x     = (const float*)d_in[0];
    const int*   ei    = (const int*)d_in[1];
    const float* msg_W = (const float*)d_in[2];
    const float* msg_b = (const float*)d_in[3];
    const float* upd_W = (const float*)d_in[4];
    const float* upd_b = (const float*)d_in[5];
    float* outp = (float*)d_out;

    int N = in_sizes[0] / D;
    int E = in_sizes[1] / 2;
    int L = in_sizes[3] / D;
    if (N > MAXN || E > MAXE) return;

    const int* src = ei;
    const int* dst = ei + E;

    float *p_v, *p_h;
    __half* p_t16;
    int *p_deg;
    cudaGetSymbolAddress((void**)&p_v,   g_v);
    cudaGetSymbolAddress((void**)&p_t16, g_t16);
    cudaGetSymbolAddress((void**)&p_h,   g_h);
    cudaGetSymbolAddress((void**)&p_deg, g_deg);

    const int SMEM = (3 * 128 * AS + 128 + 512 + 128) * (int)sizeof(float);
    static bool init_done = false;
    static cudaStream_t s1;
    static cudaEvent_t ev_fork, ev_join;
    if (!init_done) {
        cudaFuncSetAttribute(gemm_hyp_tc_kernel,
                             cudaFuncAttributeMaxDynamicSharedMemorySize, SMEM);
        cudaStreamCreateWithFlags(&s1, cudaStreamNonBlocking);
        cudaEventCreateWithFlags(&ev_fork, cudaEventDisableTiming);
        cudaEventCreateWithFlags(&ev_join, cudaEventDisableTiming);
        init_done = true;
    }

    cudaStream_t s0 = 0;

    // ---- fork: CSR build on side stream (independent of prep + msg GEMM) ----
    cudaEventRecord(ev_fork, s0);
    cudaStreamWaitEvent(s1, ev_fork, 0);
    zero_int_kernel<<<(N + 255) / 256, 256, 0, s1>>>(p_deg, N);
    hist_kernel<<<(E + 255) / 256, 256, 0, s1>>>(dst, E);
    scan_kernel<<<1, 1024, 0, s1>>>(N);
    fill_kernel<<<(E + 255) / 256, 256, 0, s1>>>(src, dst, E);
    cudaEventRecord(ev_join, s1);

    int gemm_blocks  = (N + 127) / 128;
    int warp_blocksN = (N * 32 + 255) / 256;

    prep_log0_kernel<<<warp_blocksN, 256>>>(x, p_v, N);

    bool joined = false;
    const float* v_in = p_v;
    for (int l = 0; l < L; l++) {
        gemm_hyp_tc_kernel<<<gemm_blocks, 512, SMEM>>>(v_in, msg_W + (size_t)l * D * D,
                                                       msg_b + (size_t)l * D,
                                                       nullptr, p_t16, N, 0);
        if (!joined) { cudaStreamWaitEvent(s0, ev_join, 0); joined = true; }
        agg_kernel<<<warp_blocksN, 256>>>(p_v, N);
        if (l == L - 1) {
            gemm_hyp_tc_kernel<<<gemm_blocks, 512, SMEM>>>(p_v, upd_W + (size_t)l * D * D,
                                                           upd_b + (size_t)l * D,
                                                           outp, nullptr, N, 1);
        } else {
            gemm_hyp_tc_kernel<<<gemm_blocks, 512, SMEM>>>(p_v, upd_W + (size_t)l * D * D,
                                                           upd_b + (size_t)l * D,
                                                           p_h, nullptr, N, 2);
            v_in = p_h;
        }
    }
}

// round 5
// speedup vs baseline: 3.7008x; 1.2709x over previous
#include <cuda_runtime.h>
#include <cuda_fp16.h>
#include <math.h>
#include <stdint.h>

#define EPS 1e-5f
#define MAX_NORM 0.95f
#define D 128
#define MAXN 50000
#define MAXE 800000

// ---------------- scratch (static device globals) ---------------------------
__device__ float  g_v[MAXN * D];     // tangent vectors (GEMM input)
__device__ __half g_t16[MAXN * D];   // fp16 message tangents (gather source)
__device__ float  g_h[MAXN * D];     // inter-layer tangent state (fp32)
__device__ int    g_deg[MAXN];
__device__ int    g_off[MAXN + 1];
__device__ int    g_cur[MAXN];
__device__ int    g_csrc[MAXE];

// ---------------- scalar chains ---------------------------------------------
__device__ __forceinline__ float s_log0(float n) {
    float nm  = fmaxf(n, EPS);
    float arg = fminf(nm, 1.0f - EPS);
    return atanhf(arg) / nm;
}
__device__ __forceinline__ float chain_epl(float n) {
    float nm = fmaxf(n, EPS);
    float a  = tanhf(nm) / nm;
    float na = n * a;
    float b  = (na > MAX_NORM) ? MAX_NORM / fmaxf(na, EPS) : 1.0f;
    float nb = na * b;
    float nbm = fmaxf(nb, EPS);
    float arg = fminf(nbm, 1.0f - EPS);
    float c  = atanhf(arg) / nbm;
    return a * b * c;
}
__device__ __forceinline__ float chain_ep(float n) {
    float nm = fmaxf(n, EPS);
    float a  = tanhf(nm) / nm;
    float na = n * a;
    float b  = (na > MAX_NORM) ? MAX_NORM / fmaxf(na, EPS) : 1.0f;
    return a * b;
}

// ---------------- fp16 mma helper -------------------------------------------
__device__ __forceinline__ void mma_f16(float* d, uint32_t a0, uint32_t a1,
                                        uint32_t a2, uint32_t a3,
                                        uint32_t b0, uint32_t b1) {
    asm volatile(
        "mma.sync.aligned.m16n8k16.row.col.f32.f16.f16.f32 "
        "{%0,%1,%2,%3}, {%4,%5,%6,%7}, {%8,%9}, {%0,%1,%2,%3};\n"
        : "+f"(d[0]), "+f"(d[1]), "+f"(d[2]), "+f"(d[3])
        : "r"(a0), "r"(a1), "r"(a2), "r"(a3), "r"(b0), "r"(b1));
}
// split float pair into fp16 hi + fp16 residual lo (packed half2 words)
__device__ __forceinline__ void split2(float x, float y, uint32_t& hi, uint32_t& lo) {
    __half2 h = __floats2half2_rn(x, y);
    float2 hf = __half22float2(h);
    __half2 l = __floats2half2_rn(x - hf.x, y - hf.y);
    hi = *reinterpret_cast<uint32_t*>(&h);
    lo = *reinterpret_cast<uint32_t*>(&l);
}

// ---------------- CSR construction ------------------------------------------
__global__ void zero_int_kernel(int* __restrict__ p, int n) {
    int i = blockIdx.x * blockDim.x + threadIdx.x;
    if (i < n) p[i] = 0;
}
__global__ void hist_kernel(const int* __restrict__ dst, int E) {
    int e = blockIdx.x * blockDim.x + threadIdx.x;
    if (e < E) atomicAdd(&g_deg[dst[e]], 1);
}
__global__ void scan_kernel(int N) {
    int lane = threadIdx.x & 31, wid = threadIdx.x >> 5;
    __shared__ int wsum[32];
    __shared__ int running;
    if (threadIdx.x == 0) running = 0;
    __syncthreads();
    for (int base = 0; base < N; base += 1024) {
        int i = base + (int)threadIdx.x;
        int v = (i < N) ? g_deg[i] : 0;
        int x = v;
#pragma unroll
        for (int o = 1; o < 32; o <<= 1) {
            int y = __shfl_up_sync(0xffffffffu, x, o);
            if (lane >= o) x += y;
        }
        if (lane == 31) wsum[wid] = x;
        __syncthreads();
        if (wid == 0) {
            int s = wsum[lane];
#pragma unroll
            for (int o = 1; o < 32; o <<= 1) {
                int y = __shfl_up_sync(0xffffffffu, s, o);
                if (lane >= o) s += y;
            }
            wsum[lane] = s;
        }
        __syncthreads();
        int warp_prefix = (wid == 0) ? 0 : wsum[wid - 1];
        int excl = running + warp_prefix + (x - v);
        if (i < N) { g_off[i] = excl; g_cur[i] = excl; }
        int tile_total = wsum[31];
        __syncthreads();
        if (threadIdx.x == 0) running += tile_total;
        __syncthreads();
    }
    if (threadIdx.x == 0) g_off[N] = running;
}
__global__ void fill_kernel(const int* __restrict__ src, const int* __restrict__ dst, int E) {
    int e = blockIdx.x * blockDim.x + threadIdx.x;
    if (e < E) {
        int p = atomicAdd(&g_cur[dst[e]], 1);
        g_csrc[p] = src[e];
    }
}

// ---------------- prep: v = log0(x) -----------------------------------------
__global__ void prep_log0_kernel(const float* __restrict__ in, float* __restrict__ out, int N) {
    int w    = (blockIdx.x * blockDim.x + threadIdx.x) >> 5;
    int lane = threadIdx.x & 31;
    if (w >= N) return;
    float4 v = *reinterpret_cast<const float4*>(&in[(size_t)w * D + lane * 4]);
    float p = v.x * v.x + v.y * v.y + v.z * v.z + v.w * v.w;
#pragma unroll
    for (int off = 16; off; off >>= 1) p += __shfl_xor_sync(0xffffffffu, p, off);
    float s = s_log0(sqrtf(p));
    v.x *= s; v.y *= s; v.z *= s; v.w *= s;
    *reinterpret_cast<float4*>(&out[(size_t)w * D + lane * 4]) = v;
}

// ---------------- fused gather(fp16) + mean + chain_epl ---------------------
__global__ void agg_kernel(float* __restrict__ out, int N) {
    int w    = (blockIdx.x * blockDim.x + threadIdx.x) >> 5;
    int lane = threadIdx.x & 31;
    if (w >= N) return;
    int beg = g_off[w], end = g_off[w + 1];
    float ax = 0.f, ay = 0.f, az = 0.f, aw = 0.f;
    int e = beg;
    int col = lane * 4;
#pragma unroll 1
    for (; e + 4 <= end; e += 4) {
        int s0 = g_csrc[e], s1 = g_csrc[e + 1], s2 = g_csrc[e + 2], s3 = g_csrc[e + 3];
        uint2 u0 = *reinterpret_cast<const uint2*>(&g_t16[(size_t)s0 * D + col]);
        uint2 u1 = *reinterpret_cast<const uint2*>(&g_t16[(size_t)s1 * D + col]);
        uint2 u2 = *reinterpret_cast<const uint2*>(&g_t16[(size_t)s2 * D + col]);
        uint2 u3 = *reinterpret_cast<const uint2*>(&g_t16[(size_t)s3 * D + col]);
        float2 a, b;
        a = __half22float2(*(__half2*)&u0.x); b = __half22float2(*(__half2*)&u0.y);
        ax += a.x; ay += a.y; az += b.x; aw += b.y;
        a = __half22float2(*(__half2*)&u1.x); b = __half22float2(*(__half2*)&u1.y);
        ax += a.x; ay += a.y; az += b.x; aw += b.y;
        a = __half22float2(*(__half2*)&u2.x); b = __half22float2(*(__half2*)&u2.y);
        ax += a.x; ay += a.y; az += b.x; aw += b.y;
        a = __half22float2(*(__half2*)&u3.x); b = __half22float2(*(__half2*)&u3.y);
        ax += a.x; ay += a.y; az += b.x; aw += b.y;
    }
    for (; e < end; e++) {
        int s0 = g_csrc[e];
        uint2 u0 = *reinterpret_cast<const uint2*>(&g_t16[(size_t)s0 * D + col]);
        float2 a = __half22float2(*(__half2*)&u0.x);
        float2 b = __half22float2(*(__half2*)&u0.y);
        ax += a.x; ay += a.y; az += b.x; aw += b.y;
    }
    float inv = 1.0f / fmaxf((float)(end - beg), 1.0f);
    ax *= inv; ay *= inv; az *= inv; aw *= inv;
    float p = ax * ax + ay * ay + az * az + aw * aw;
#pragma unroll
    for (int off = 16; off; off >>= 1) p += __shfl_xor_sync(0xffffffffu, p, off);
    float s = chain_epl(sqrtf(p));
    float4 o = make_float4(ax * s, ay * s, az * s, aw * s);
    *reinterpret_cast<float4*>(&out[(size_t)w * D + col]) = o;
}

// ---------------- 3x fp16-split tensor-core GEMM + hyperbolic epilogue ------
// CTA: 128x128 output tile, K=128 resident. 16 warps, warp tile 32x32.
// A,W pre-split to fp16 hi/lo at load; mainloop = pure LDS + m16n8k16 MMA.
// mode 0: chain_epl, fp16 store (message tangents)
// mode 1: chain_ep,  fp32 store (final output)
// mode 2: chain_epl, fp32 store (inter-layer tangent)
#define STR 68   // half2-word stride per row: 68 mod 32 == 4 -> banks 4g+c, conflict-free

__global__ __launch_bounds__(512) void gemm_hyp_tc_kernel(
    const float* __restrict__ V, const float* __restrict__ W,
    const float* __restrict__ bias, float* __restrict__ out,
    __half* __restrict__ out16, int N, int mode)
{
    extern __shared__ uint32_t smem_u[];
    uint32_t* Ahi = smem_u;                 // [128][STR] half2 words
    uint32_t* Alo = Ahi + 128 * STR;
    uint32_t* Whi = Alo + 128 * STR;
    uint32_t* Wlo = Whi + 128 * STR;
    float* bias_s = (float*)(Wlo + 128 * STR);  // [128]
    float* red    = bias_s + 128;               // [128][4]
    float* scl    = red + 512;                  // [128]

    int tid  = threadIdx.x;
    int lane = tid & 31;
    int warp = tid >> 5;
    int rbase = (warp >> 2) * 32;   // 4 row groups
    int cbase = (warp & 3) * 32;    // 4 col groups
    int m0 = blockIdx.x * 128;

    if (tid < 128) bias_s[tid] = bias[tid];

    // ---- load tiles, split to fp16 hi/lo ----
#pragma unroll
    for (int i = 0; i < 8; i++) {
        int idx = tid + i * 512;            // 4096 float4 slots
        int row = idx >> 5;
        int c4  = (idx & 31) * 4;           // float col, multiple of 4
        int wofs = row * STR + (c4 >> 1);   // half2-word offset

        float4 av = make_float4(0.f, 0.f, 0.f, 0.f);
        int gm = m0 + row;
        if (gm < N) av = *reinterpret_cast<const float4*>(&V[(size_t)gm * D + c4]);
        uint32_t h0, l0, h1, l1;
        split2(av.x, av.y, h0, l0);
        split2(av.z, av.w, h1, l1);
        Ahi[wofs] = h0; Ahi[wofs + 1] = h1;
        Alo[wofs] = l0; Alo[wofs + 1] = l1;

        float4 wv = *reinterpret_cast<const float4*>(&W[(size_t)row * D + c4]);
        split2(wv.x, wv.y, h0, l0);
        split2(wv.z, wv.w, h1, l1);
        Whi[wofs] = h0; Whi[wofs + 1] = h1;
        Wlo[wofs] = l0; Wlo[wofs + 1] = l1;
    }
    __syncthreads();

    float acc[2][4][4];
#pragma unroll
    for (int rt = 0; rt < 2; rt++)
#pragma unroll
        for (int ct = 0; ct < 4; ct++)
#pragma unroll
            for (int q = 0; q < 4; q++) acc[rt][ct][q] = 0.0f;

    int c = lane & 3;
    int g = lane >> 2;

#pragma unroll
    for (int ks = 0; ks < 8; ks++) {
        int k0 = ks * 8;                    // word offset of this k16 step
        uint32_t ah[2][4], al[2][4];
#pragma unroll
        for (int rt = 0; rt < 2; rt++) {
            int r0 = rbase + rt * 16 + g;
            int b0 = r0 * STR + k0 + c;
            int b1 = (r0 + 8) * STR + k0 + c;
            ah[rt][0] = Ahi[b0];     ah[rt][1] = Ahi[b1];
            ah[rt][2] = Ahi[b0 + 4]; ah[rt][3] = Ahi[b1 + 4];
            al[rt][0] = Alo[b0];     al[rt][1] = Alo[b1];
            al[rt][2] = Alo[b0 + 4]; al[rt][3] = Alo[b1 + 4];
        }
#pragma unroll
        for (int ct = 0; ct < 4; ct++) {
            int col = cbase + ct * 8 + g;
            int wb = col * STR + k0 + c;
            uint32_t bh0 = Whi[wb], bh1 = Whi[wb + 4];
            uint32_t bl0 = Wlo[wb], bl1 = Wlo[wb + 4];
#pragma unroll
            for (int rt = 0; rt < 2; rt++) {
                mma_f16(acc[rt][ct], ah[rt][0], ah[rt][1], ah[rt][2], ah[rt][3], bh0, bh1);
                mma_f16(acc[rt][ct], ah[rt][0], ah[rt][1], ah[rt][2], ah[rt][3], bl0, bl1);
                mma_f16(acc[rt][ct], al[rt][0], al[rt][1], al[rt][2], al[rt][3], bh0, bh1);
            }
        }
    }

    // ---- epilogue: bias add + per-row sumsq ----
    float prow[2][2];
#pragma unroll
    for (int rt = 0; rt < 2; rt++) {
        prow[rt][0] = 0.f; prow[rt][1] = 0.f;
#pragma unroll
        for (int ct = 0; ct < 4; ct++) {
            int colb = cbase + ct * 8 + 2 * c;
            float u0 = acc[rt][ct][0] + bias_s[colb];
            float u1 = acc[rt][ct][1] + bias_s[colb + 1];
            float u2 = acc[rt][ct][2] + bias_s[colb];
            float u3 = acc[rt][ct][3] + bias_s[colb + 1];
            acc[rt][ct][0] = u0; acc[rt][ct][1] = u1;
            acc[rt][ct][2] = u2; acc[rt][ct][3] = u3;
            prow[rt][0] += u0 * u0 + u1 * u1;
            prow[rt][1] += u2 * u2 + u3 * u3;
        }
#pragma unroll
        for (int o = 1; o < 4; o <<= 1) {
            prow[rt][0] += __shfl_xor_sync(0xffffffffu, prow[rt][0], o);
            prow[rt][1] += __shfl_xor_sync(0xffffffffu, prow[rt][1], o);
        }
    }
    int cg = warp & 3;
    if (c == 0) {
#pragma unroll
        for (int rt = 0; rt < 2; rt++) {
            int r0 = rbase + rt * 16 + g;
            red[r0 * 4 + cg]       = prow[rt][0];
            red[(r0 + 8) * 4 + cg] = prow[rt][1];
        }
    }
    __syncthreads();
    if (tid < 128) {
        float s = red[tid * 4] + red[tid * 4 + 1] + red[tid * 4 + 2] + red[tid * 4 + 3];
        float n = sqrtf(s);
        scl[tid] = (mode == 1) ? chain_ep(n) : chain_epl(n);
    }
    __syncthreads();

    // ---- scaled store ----
#pragma unroll
    for (int rt = 0; rt < 2; rt++) {
        int r0 = rbase + rt * 16 + g;
        float s0 = scl[r0];
        float s1 = scl[r0 + 8];
        int gm0 = m0 + r0;
        int gm1 = gm0 + 8;
#pragma unroll
        for (int ct = 0; ct < 4; ct++) {
            int colb = cbase + ct * 8 + 2 * c;
            if (mode == 0) {
                if (gm0 < N) {
                    __half2 hv = __floats2half2_rn(acc[rt][ct][0] * s0, acc[rt][ct][1] * s0);
                    *reinterpret_cast<__half2*>(&out16[(size_t)gm0 * D + colb]) = hv;
                }
                if (gm1 < N) {
                    __half2 hv = __floats2half2_rn(acc[rt][ct][2] * s1, acc[rt][ct][3] * s1);
                    *reinterpret_cast<__half2*>(&out16[(size_t)gm1 * D + colb]) = hv;
                }
            } else {
                if (gm0 < N) {
                    float2 o = make_float2(acc[rt][ct][0] * s0, acc[rt][ct][1] * s0);
                    *reinterpret_cast<float2*>(&out[(size_t)gm0 * D + colb]) = o;
                }
                if (gm1 < N) {
                    float2 o = make_float2(acc[rt][ct][2] * s1, acc[rt][ct][3] * s1);
                    *reinterpret_cast<float2*>(&out[(size_t)gm1 * D + colb]) = o;
                }
            }
        }
    }
}

// ---------------- host ------------------------------------------------------
extern "C" void kernel_launch(void* const* d_in, const int* in_sizes, int n_in,
                              void* d_out, int out_size)
{
    const float* x     = (const float*)d_in[0];
    const int*   ei    = (const int*)d_in[1];
    const float* msg_W = (const float*)d_in[2];
    const float* msg_b = (const float*)d_in[3];
    const float* upd_W = (const float*)d_in[4];
    const float* upd_b = (const float*)d_in[5];
    float* outp = (float*)d_out;

    int N = in_sizes[0] / D;
    int E = in_sizes[1] / 2;
    int L = in_sizes[3] / D;
    if (N > MAXN || E > MAXE) return;

    const int* src = ei;
    const int* dst = ei + E;

    float *p_v, *p_h;
    __half* p_t16;
    int *p_deg;
    cudaGetSymbolAddress((void**)&p_v,   g_v);
    cudaGetSymbolAddress((void**)&p_t16, g_t16);
    cudaGetSymbolAddress((void**)&p_h,   g_h);
    cudaGetSymbolAddress((void**)&p_deg, g_deg);

    const int SMEM = (4 * 128 * STR + 128 + 512 + 128) * (int)sizeof(uint32_t);
    static bool init_done = false;
    static cudaStream_t s1;
    static cudaEvent_t ev_fork, ev_join;
    if (!init_done) {
        cudaFuncSetAttribute(gemm_hyp_tc_kernel,
                             cudaFuncAttributeMaxDynamicSharedMemorySize, SMEM);
        cudaStreamCreateWithFlags(&s1, cudaStreamNonBlocking);
        cudaEventCreateWithFlags(&ev_fork, cudaEventDisableTiming);
        cudaEventCreateWithFlags(&ev_join, cudaEventDisableTiming);
        init_done = true;
    }

    cudaStream_t s0 = 0;

    // ---- fork: CSR build on side stream ----
    cudaEventRecord(ev_fork, s0);
    cudaStreamWaitEvent(s1, ev_fork, 0);
    zero_int_kernel<<<(N + 255) / 256, 256, 0, s1>>>(p_deg, N);
    hist_kernel<<<(E + 255) / 256, 256, 0, s1>>>(dst, E);
    scan_kernel<<<1, 1024, 0, s1>>>(N);
    fill_kernel<<<(E + 255) / 256, 256, 0, s1>>>(src, dst, E);
    cudaEventRecord(ev_join, s1);

    int gemm_blocks  = (N + 127) / 128;
    int warp_blocksN = (N * 32 + 255) / 256;

    prep_log0_kernel<<<warp_blocksN, 256>>>(x, p_v, N);

    bool joined = false;
    const float* v_in = p_v;
    for (int l = 0; l < L; l++) {
        gemm_hyp_tc_kernel<<<gemm_blocks, 512, SMEM>>>(v_in, msg_W + (size_t)l * D * D,
                                                       msg_b + (size_t)l * D,
                                                       nullptr, p_t16, N, 0);
        if (!joined) { cudaStreamWaitEvent(s0, ev_join, 0); joined = true; }
        agg_kernel<<<warp_blocksN, 256>>>(p_v, N);
        if (l == L - 1) {
            gemm_hyp_tc_kernel<<<gemm_blocks, 512, SMEM>>>(p_v, upd_W + (size_t)l * D * D,
                                                           upd_b + (size_t)l * D,
                                                           outp, nullptr, N, 1);
        } else {
            gemm_hyp_tc_kernel<<<gemm_blocks, 512, SMEM>>>(p_v, upd_W + (size_t)l * D * D,
                                                           upd_b + (size_t)l * D,
                                                           p_h, nullptr, N, 2);
            v_in = p_h;
        }
    }
}